// round 6
// baseline (speedup 1.0000x reference)
#include <cuda_runtime.h>
#include <cuda_fp16.h>

#define HID 128
#define NS  12
#define PAD 132          // weight row pitch (floats)
#define NW  28           // warps per CTA (14 pairs)
#define PAIRS (NW/2)
#define NB  8            // batch elements per task
#define THREADS (NW*32)
#define GRID 148

typedef unsigned long long ull;

// ---- shared memory layout (float offsets) ----
#define OW1   0                      // W1^T  [128][132]  (Wt[k][h] = W[h][k])
#define OW2   16896                  // W2^T  [128][132]
#define OW0   33792                  // W0^T  [12][132]
#define OCEN  35376                  // 12 (pad 16)
#define OINV  35392                  // 12 (pad 16)
#define OWARP 35408
#define WSTRIDE 1552                 // BigA 1024 + V1h 512 + VX 16   (per TASK)
#define SMEM_FLOATS (OWARP + PAIRS*WSTRIDE)   // 57136 floats = 228544 B

__device__ float g_R3[HID];
__device__ float g_c3;

__global__ void init_kernel(const float* __restrict__ W3, const float* __restrict__ b3,
                            const float* __restrict__ Wout, const float* __restrict__ bout)
{
    int h = threadIdx.x;  // 0..127
    float acc = 0.f;
    for (int j = 0; j < HID; ++j) acc = fmaf(Wout[j], W3[j*HID + h], acc);
    g_R3[h] = acc;
    if (h == 0) {
        float c = bout[0];
        for (int j = 0; j < HID; ++j) c = fmaf(Wout[j], b3[j], c);
        g_c3 = c;
    }
}

// ---- packed f32x2 helpers ----
__device__ __forceinline__ ull ffma2(ull a, ull b, ull c)
{
    ull d;
    asm("fma.rn.f32x2 %0, %1, %2, %3;" : "=l"(d) : "l"(a), "l"(b), "l"(c));
    return d;
}
__device__ __forceinline__ ull pack2(float lo, float hi)
{
    ull d; asm("mov.b64 %0, {%1, %2};" : "=l"(d) : "f"(lo), "f"(hi)); return d;
}
__device__ __forceinline__ void unpack2(ull v, float& lo, float& hi)
{
    asm("mov.b64 {%0, %1}, %2;" : "=f"(lo), "=f"(hi) : "l"(v));
}
__device__ __forceinline__ ull shflx(ull v, int src)
{
    return __shfl_sync(0xffffffffu, v, src);
}
// pair barrier: 2 warps, 64 threads, named barrier id = pair (0..13)
__device__ __forceinline__ void bar_pair(int id)
{
    asm volatile("bar.sync %0, 64;" :: "r"(id) : "memory");
}

// Fast tanh: 1 - 2/(e^{2x}+1).
__device__ __forceinline__ float ftanh(float x)
{
    float e = __expf(2.0f * x);
    return 1.0f - __fdividef(2.0f, e + 1.0f);
}

// ---- bank swizzle for BigA [128][8] fp32 rows (32B rows) ----
__device__ __forceinline__ int physrow(int h) { return (h & ~3) | ((h ^ (h >> 2)) & 3); }
__device__ __forceinline__ int cswap(int h)   { return ((h >> 2) ^ (h >> 4)) & 1; }

__device__ __forceinline__ void store8(float* buf, int h, const float t[8])
{
    float* rp = buf + physrow(h)*8;
    int b = cswap(h);
    *(float4*)(rp + 4*b)     = make_float4(t[0], t[1], t[2], t[3]);
    *(float4*)(rp + 4*(b^1)) = make_float4(t[4], t[5], t[6], t[7]);
}

// ---- fp16 side buffer V1h: 16B rows, XOR layout; conflict-free for
//      write h=4l+t (t fixed) and read h=l+32M patterns ----
__device__ __forceinline__ int off16f(int h)   // float offset of 16B row
{
    return ((h & 3) * 32 + ((h >> 2) ^ (2 * (h & 3)))) * 4;
}

// Forward matvec (smem input): this warp computes cols c0, c0+1 (c0 = 4l+2wa).
__device__ __forceinline__ void fwd2(const float* __restrict__ Wt,
                                     const float* __restrict__ biasg,
                                     const float* __restrict__ inq,
                                     ull z[2][4], int c0)
{
    float2 bb = *(const float2*)&biasg[c0];
    z[0][0] = z[0][1] = z[0][2] = z[0][3] = pack2(bb.x, bb.x);
    z[1][0] = z[1][1] = z[1][2] = z[1][3] = pack2(bb.y, bb.y);

#pragma unroll 4
    for (int k = 0; k < HID; ++k) {
        float2 wv = *(const float2*)&Wt[k*PAD + c0];     // contiguous LDS.64
        const float* rp = inq + physrow(k)*8;
        int b = cswap(k);
        ulonglong2 xa = *(const ulonglong2*)(rp + 4*b);
        ulonglong2 xb = *(const ulonglong2*)(rp + 4*(b^1));
        ull x[4] = {xa.x, xa.y, xb.x, xb.y};
        ull w0 = pack2(wv.x, wv.x), w1 = pack2(wv.y, wv.y);
#pragma unroll
        for (int pp = 0; pp < 4; ++pp) {
            z[0][pp] = ffma2(w0, x[pp], z[0][pp]);
            z[1][pp] = ffma2(w1, x[pp], z[1][pp]);
        }
    }
}

// Input layer (K=12), x pairs by shuffle.
__device__ __forceinline__ void fwd2x(const float* __restrict__ Wt,
                                      const float* __restrict__ biasg,
                                      ull ua, ull ub, ull z[2][4], int c0)
{
    float2 bb = *(const float2*)&biasg[c0];
    z[0][0] = z[0][1] = z[0][2] = z[0][3] = pack2(bb.x, bb.x);
    z[1][0] = z[1][1] = z[1][2] = z[1][3] = pack2(bb.y, bb.y);

#pragma unroll
    for (int k = 0; k < NS; ++k) {
        ull x[4];
#pragma unroll
        for (int pp = 0; pp < 4; ++pp)
            x[pp] = (k < 8) ? shflx(ua, 4*k + pp) : shflx(ub, 4*(k-8) + pp);
        float2 wv = *(const float2*)&Wt[k*PAD + c0];
        ull w0 = pack2(wv.x, wv.x), w1 = pack2(wv.y, wv.y);
#pragma unroll
        for (int pp = 0; pp < 4; ++pp) {
            z[0][pp] = ffma2(w0, x[pp], z[0][pp]);
            z[1][pp] = ffma2(w1, x[pp], z[1][pp]);
        }
    }
}

// Backward vecmat: r[m'][pp] = sum_h g[h][pp] * Wt[(l + 32*(2wa+m'))][h]
__device__ __forceinline__ void bwd2(const float* __restrict__ Wt,
                                     const float* __restrict__ gin,
                                     ull r[2][4], int l, int wa)
{
    r[0][0]=r[0][1]=r[0][2]=r[0][3]=0ull;
    r[1][0]=r[1][1]=r[1][2]=r[1][3]=0ull;
    int k0 = l + 64*wa;        // m'=0 row; m'=1 row = k0+32

#pragma unroll 2
    for (int c = 0; c < 32; ++c) {          // chunks of 4 h-rows
        int perm = c & 3, b = (c ^ (c >> 2)) & 1;
        ull g[4][4];
#pragma unroll
        for (int sg = 0; sg < 4; ++sg) {
            const float* rp = gin + (4*c + (sg ^ perm))*8;   // = physrow(4c+sg)
            ulonglong2 ga = *(const ulonglong2*)(rp + 4*b);
            ulonglong2 gb = *(const ulonglong2*)(rp + 4*(b^1));
            g[sg][0] = ga.x; g[sg][1] = ga.y; g[sg][2] = gb.x; g[sg][3] = gb.y;
        }
#pragma unroll
        for (int m = 0; m < 2; ++m) {
            float4 w4 = *(const float4*)&Wt[(k0 + 32*m)*PAD + 4*c]; // conflict-free
            float wm[4] = {w4.x, w4.y, w4.z, w4.w};
#pragma unroll
            for (int sg = 0; sg < 4; ++sg) {
                ull w2 = pack2(wm[sg], wm[sg]);
#pragma unroll
                for (int pp = 0; pp < 4; ++pp)
                    r[m][pp] = ffma2(w2, g[sg][pp], r[m][pp]);
            }
        }
    }
}

__global__ __launch_bounds__(THREADS, 1)
void mlp_kernel(const float* __restrict__ state,
                const float* __restrict__ safe_m, const float* __restrict__ safe_l,
                const float* __restrict__ W0, const float* __restrict__ b0,
                const float* __restrict__ W1, const float* __restrict__ b1,
                const float* __restrict__ W2, const float* __restrict__ b2,
                float* __restrict__ out, int nb)
{
    extern __shared__ float s[];
    int tid = threadIdx.x;

    // ---- stage weights into SMEM (transposed, PAD-pitched) ----
    for (int i = tid; i < HID*HID; i += THREADS) {
        int h = i >> 7, k = i & 127;
        s[OW1 + k*PAD + h] = W1[i];
        s[OW2 + k*PAD + h] = W2[i];
    }
    for (int i = tid; i < HID*NS; i += THREADS) {
        int h = i / NS, k = i - h*NS;
        s[OW0 + k*PAD + h] = W0[i];
    }
    if (tid < NS) {
        float m = safe_m[tid], lo = safe_l[tid];
        s[OCEN + tid] = 0.5f * (m + lo);
        s[OINV + tid] = 2.0f / (m - lo);
    }
    __syncthreads();

    int w = tid >> 5, l = tid & 31;
    int pair = w >> 1, wa = w & 1;
    float* BigA = s + OWARP + pair*WSTRIDE;  // [128][8] fp32: V0 -> V1 -> g2 -> g1 -> g0
    float* V1h  = BigA + 1024;               // fp16 rows (also J-partial float area later)
    float* VX   = BigA + 1536;               // 16 floats exchange

    int c0 = 4*l + 2*wa;                     // this warp's forward cols / row ids

    int gw = blockIdx.x + GRID * pair;       // one task per warp-pair
    int quads = (nb + NB - 1) / NB;
    if (gw < quads) {
        int base = gw * NB;

        // ---- A: inputs into 2 register pairs per lane (both warps identically) ----
        ull ua, ub;
        {
            int p0 = 2*(l & 3);
            int ka = l >> 2;                  // 0..7
            int kb = 8 + ((l >> 2) & 3);      // 8..11
            int i0 = base + p0, i1 = base + p0 + 1;
            float a0 = (i0 < nb) ? state[i0*NS + ka] : 0.f;
            float a1 = (i1 < nb) ? state[i1*NS + ka] : 0.f;
            float cc0 = (i0 < nb) ? state[i0*NS + kb] : 0.f;
            float cc1 = (i1 < nb) ? state[i1*NS + kb] : 0.f;
            float ca = s[OCEN + ka], ia = s[OINV + ka];
            float cb = s[OCEN + kb], ib = s[OINV + kb];
            ua = pack2((a0 - ca)*ia, (a1 - ca)*ia);
            ub = pack2((cc0 - cb)*ib, (cc1 - cb)*ib);
        }

        ull z[2][4];
        float t[8];

        // ---- B: input layer + tanh -> V0 (BigA rows c0, c0+1) ----
        fwd2x(s + OW0, b0, ua, ub, z, c0);
#pragma unroll
        for (int j = 0; j < 2; ++j) {
#pragma unroll
            for (int pp = 0; pp < 4; ++pp) unpack2(z[j][pp], t[2*pp], t[2*pp+1]);
#pragma unroll
            for (int p = 0; p < 8; ++p) t[p] = ftanh(t[p]);
            store8(BigA, c0 + j, t);
        }
        bar_pair(pair);

        // ---- C: layer 1 + tanh -> V1 (in place) + fp16 copy ----
        fwd2(s + OW1, b1, BigA, z, c0);
        bar_pair(pair);                       // all V0 reads done (both warps)
#pragma unroll
        for (int j = 0; j < 2; ++j) {
#pragma unroll
            for (int pp = 0; pp < 4; ++pp) unpack2(z[j][pp], t[2*pp], t[2*pp+1]);
#pragma unroll
            for (int p = 0; p < 8; ++p) t[p] = ftanh(t[p]);
            store8(BigA, c0 + j, t);
            __half2 h0 = __floats2half2_rn(t[0], t[1]);
            __half2 h1 = __floats2half2_rn(t[2], t[3]);
            __half2 h2 = __floats2half2_rn(t[4], t[5]);
            __half2 h3 = __floats2half2_rn(t[6], t[7]);
            uint4 u;
            u.x = *(unsigned*)&h0; u.y = *(unsigned*)&h1;
            u.z = *(unsigned*)&h2; u.w = *(unsigned*)&h3;
            *(uint4*)&V1h[off16f(c0 + j)] = u;
        }
        bar_pair(pair);

        // ---- D: layer 2 + tanh; vout = R3.V2 ; g2 -> BigA ----
        fwd2(s + OW2, b2, BigA, z, c0);
        bar_pair(pair);                       // all V1 reads done
        {
            ull vo[4] = {0ull, 0ull, 0ull, 0ull};
            float2 r2 = *(const float2*)&g_R3[c0];
            float rj[2] = {r2.x, r2.y};
#pragma unroll
            for (int j = 0; j < 2; ++j) {
                ull rj2 = pack2(rj[j], rj[j]);
#pragma unroll
                for (int pp = 0; pp < 4; ++pp) unpack2(z[j][pp], t[2*pp], t[2*pp+1]);
#pragma unroll
                for (int p = 0; p < 8; ++p) t[p] = ftanh(t[p]);
#pragma unroll
                for (int pp = 0; pp < 4; ++pp)
                    vo[pp] = ffma2(rj2, pack2(t[2*pp], t[2*pp+1]), vo[pp]);
                float gq[8];
#pragma unroll
                for (int p = 0; p < 8; ++p) gq[p] = rj[j] * (1.f - t[p]*t[p]);
                store8(BigA, c0 + j, gq);
            }
            float vout[8];
#pragma unroll
            for (int pp = 0; pp < 4; ++pp) unpack2(vo[pp], vout[2*pp], vout[2*pp+1]);
#pragma unroll
            for (int p = 0; p < 8; ++p) {
                float v = vout[p];
#pragma unroll
                for (int off = 16; off > 0; off >>= 1)
                    v += __shfl_xor_sync(0xffffffffu, v, off);
                vout[p] = v;
            }
            if (wa == 1 && l < 8) VX[l] = vout[l];
            bar_pair(pair);                   // g2 + VX visible
            if (wa == 0 && l < 8 && base + l < nb)
                out[(base + l)*13] = vout[l] + VX[l] + g_c3;
        }

        ull r[2][4];

        // ---- E: r = g2.W2 ; s1 from fp16; g1 -> BigA ----
        bwd2(s + OW2, BigA, r, l, wa);
        bar_pair(pair);                       // all g2 reads done
#pragma unroll
        for (int m = 0; m < 2; ++m) {
            int h = l + 64*wa + 32*m;
            uint4 u = *(const uint4*)&V1h[off16f(h)];
            float2 f0 = __half22float2(*(__half2*)&u.x);
            float2 f1 = __half22float2(*(__half2*)&u.y);
            float2 f2 = __half22float2(*(__half2*)&u.z);
            float2 f3 = __half22float2(*(__half2*)&u.w);
            float vp[8] = {f0.x, f0.y, f1.x, f1.y, f2.x, f2.y, f3.x, f3.y};
            float gq[8];
#pragma unroll
            for (int pp = 0; pp < 4; ++pp) {
                float r0, r1; unpack2(r[m][pp], r0, r1);
                gq[2*pp]   = r0 * (1.f - vp[2*pp]*vp[2*pp]);
                gq[2*pp+1] = r1 * (1.f - vp[2*pp+1]*vp[2*pp+1]);
            }
            store8(BigA, h, gq);
        }
        bar_pair(pair);

        // ---- F: r = g1.W1 ; s0 recompute (shfl x) ; g0 -> BigA ----
        bwd2(s + OW1, BigA, r, l, wa);
        bar_pair(pair);                       // all g1 reads done
        {
            ull z0[2][4];
#pragma unroll
            for (int m = 0; m < 2; ++m) {
                float bm = b0[l + 64*wa + 32*m];
                ull b2v = pack2(bm, bm);
#pragma unroll
                for (int pp = 0; pp < 4; ++pp) z0[m][pp] = b2v;
            }
#pragma unroll
            for (int k = 0; k < NS; ++k) {
                ull x[4];
#pragma unroll
                for (int pp = 0; pp < 4; ++pp)
                    x[pp] = (k < 8) ? shflx(ua, 4*k + pp) : shflx(ub, 4*(k-8) + pp);
#pragma unroll
                for (int m = 0; m < 2; ++m) {
                    float wv = s[OW0 + k*PAD + l + 64*wa + 32*m];
                    ull w2 = pack2(wv, wv);
#pragma unroll
                    for (int pp = 0; pp < 4; ++pp)
                        z0[m][pp] = ffma2(w2, x[pp], z0[m][pp]);
                }
            }
#pragma unroll
            for (int m = 0; m < 2; ++m) {
                int h = l + 64*wa + 32*m;
                float gq[8];
#pragma unroll
                for (int pp = 0; pp < 4; ++pp) {
                    float a, b; unpack2(z0[m][pp], a, b);
                    a = ftanh(a); b = ftanh(b);
                    float r0, r1; unpack2(r[m][pp], r0, r1);
                    gq[2*pp]   = r0 * (1.f - a*a);
                    gq[2*pp+1] = r1 * (1.f - b*b);
                }
                store8(BigA, h, gq);
            }
        }
        bar_pair(pair);

        // ---- final: J[k][p] = (sum_h g0[h][p] * W0t[k][h]) * inv[k] ----
        {
            int p  = l & 7;
            int k0 = l >> 3;                 // k = k0 + 4c, c in 0..2
            int psel = p >> 2, pw = p & 3;
            float acc[3] = {0.f, 0.f, 0.f};
            int ibeg = 16*wa;
#pragma unroll 2
            for (int ii = 0; ii < 16; ++ii) {   // h = 4i..4i+3, this warp's 64-row half
                int i = ibeg + ii;
                float4 w0 = *(const float4*)&s[OW0 + (k0    )*PAD + 4*i];
                float4 w1 = *(const float4*)&s[OW0 + (k0 + 4)*PAD + 4*i];
                float4 w2 = *(const float4*)&s[OW0 + (k0 + 8)*PAD + 4*i];
                float gv[4];
#pragma unroll
                for (int d = 0; d < 4; ++d) {
                    int h = 4*i + d;
                    gv[d] = BigA[physrow(h)*8 + 4*(psel ^ cswap(h)) + pw];
                }
                acc[0] = fmaf(w0.x, gv[0], acc[0]); acc[0] = fmaf(w0.y, gv[1], acc[0]);
                acc[0] = fmaf(w0.z, gv[2], acc[0]); acc[0] = fmaf(w0.w, gv[3], acc[0]);
                acc[1] = fmaf(w1.x, gv[0], acc[1]); acc[1] = fmaf(w1.y, gv[1], acc[1]);
                acc[1] = fmaf(w1.z, gv[2], acc[1]); acc[1] = fmaf(w1.w, gv[3], acc[1]);
                acc[2] = fmaf(w2.x, gv[0], acc[2]); acc[2] = fmaf(w2.y, gv[1], acc[2]);
                acc[2] = fmaf(w2.z, gv[2], acc[2]); acc[2] = fmaf(w2.w, gv[3], acc[2]);
            }
            float* Jp = V1h;                  // reuse fp16 area as float scratch
            if (wa == 1) {
#pragma unroll
                for (int c = 0; c < 3; ++c) Jp[l*3 + c] = acc[c];
            }
            bar_pair(pair);
            if (wa == 0 && base + p < nb) {
#pragma unroll
                for (int c = 0; c < 3; ++c) {
                    int k = k0 + 4*c;
                    out[(base + p)*13 + 1 + k] = (acc[c] + Jp[l*3 + c]) * s[OINV + k];
                }
            }
        }
    }
}

extern "C" void kernel_launch(void* const* d_in, const int* in_sizes, int n_in,
                              void* d_out, int out_size)
{
    const float* state  = (const float*)d_in[0];
    const float* safe_m = (const float*)d_in[1];
    const float* safe_l = (const float*)d_in[2];
    const float* W0     = (const float*)d_in[3];
    const float* b0     = (const float*)d_in[4];
    const float* W1     = (const float*)d_in[5];
    const float* b1     = (const float*)d_in[6];
    const float* W2     = (const float*)d_in[7];
    const float* b2     = (const float*)d_in[8];
    const float* W3     = (const float*)d_in[9];
    const float* b3     = (const float*)d_in[10];
    const float* Wout   = (const float*)d_in[11];
    const float* bout   = (const float*)d_in[12];
    float* out = (float*)d_out;

    int nb = in_sizes[0] / NS;

    cudaFuncSetAttribute(mlp_kernel, cudaFuncAttributeMaxDynamicSharedMemorySize,
                         SMEM_FLOATS * (int)sizeof(float));

    init_kernel<<<1, HID>>>(W3, b3, Wout, bout);
    mlp_kernel<<<GRID, THREADS, SMEM_FLOATS * sizeof(float)>>>(
        state, safe_m, safe_l, W0, b0, W1, b1, W2, b2, out, nb);
}

// round 7
// speedup vs baseline: 1.0778x; 1.0778x over previous
#include <cuda_runtime.h>
#include <cuda_fp16.h>

#define HID 128
#define NS  12
#define PAD 132          // weight row pitch (floats)
#define NW  28           // warps per CTA (14 pairs)
#define PAIRS (NW/2)
#define NB  8            // batch elements per task
#define THREADS (NW*32)
#define GRID 148

typedef unsigned long long ull;

// ---- shared memory layout (float offsets) ----
#define OW1   0                      // W1^T  [128][132]  (Wt[k][h] = W[h][k])
#define OW2   16896                  // W2^T  [128][132]
#define OW0   33792                  // W0^T  [12][132]
#define OCEN  35376                  // 12 (pad 16)
#define OINV  35392                  // 12 (pad 16)
#define OWARP 35408
#define WSTRIDE 1552                 // BigA 1024 + V1h 512 + VX 16   (per TASK)
#define SMEM_FLOATS (OWARP + PAIRS*WSTRIDE)   // 57136 floats = 228544 B

__device__ float g_R3[HID];
__device__ float g_c3;

__global__ void init_kernel(const float* __restrict__ W3, const float* __restrict__ b3,
                            const float* __restrict__ Wout, const float* __restrict__ bout)
{
    int h = threadIdx.x;  // 0..127
    float acc = 0.f;
    for (int j = 0; j < HID; ++j) acc = fmaf(Wout[j], W3[j*HID + h], acc);
    g_R3[h] = acc;
    if (h == 0) {
        float c = bout[0];
        for (int j = 0; j < HID; ++j) c = fmaf(Wout[j], b3[j], c);
        g_c3 = c;
    }
}

// ---- packed f32x2 helpers ----
__device__ __forceinline__ ull ffma2(ull a, ull b, ull c)
{
    ull d;
    asm("fma.rn.f32x2 %0, %1, %2, %3;" : "=l"(d) : "l"(a), "l"(b), "l"(c));
    return d;
}
__device__ __forceinline__ ull pack2(float lo, float hi)
{
    ull d; asm("mov.b64 %0, {%1, %2};" : "=l"(d) : "f"(lo), "f"(hi)); return d;
}
__device__ __forceinline__ void unpack2(ull v, float& lo, float& hi)
{
    asm("mov.b64 {%0, %1}, %2;" : "=f"(lo), "=f"(hi) : "l"(v));
}
__device__ __forceinline__ ull shflx(ull v, int src)
{
    return __shfl_sync(0xffffffffu, v, src);
}
// pair barrier: 2 warps, 64 threads, named barrier id = pair (0..13)
__device__ __forceinline__ void bar_pair(int id)
{
    asm volatile("bar.sync %0, 64;" :: "r"(id) : "memory");
}

// Fast tanh: 1 - 2/(e^{2x}+1).
__device__ __forceinline__ float ftanh(float x)
{
    float e = __expf(2.0f * x);
    return 1.0f - __fdividef(2.0f, e + 1.0f);
}

// ---- bank swizzle for BigA [128][8] fp32 rows (32B rows) ----
__device__ __forceinline__ int physrow(int h) { return (h & ~3) | ((h ^ (h >> 2)) & 3); }
__device__ __forceinline__ int cswap(int h)   { return ((h >> 2) ^ (h >> 4)) & 1; }

__device__ __forceinline__ void store8(float* buf, int h, const float t[8])
{
    float* rp = buf + physrow(h)*8;
    int b = cswap(h);
    *(float4*)(rp + 4*b)     = make_float4(t[0], t[1], t[2], t[3]);
    *(float4*)(rp + 4*(b^1)) = make_float4(t[4], t[5], t[6], t[7]);
}

// ---- fp16 side buffer V1h: 16B rows, XOR layout; conflict-free for
//      write h=2l+c and read h=l+64wa+32m patterns (bank-quad XOR-group proof) ----
__device__ __forceinline__ int off16f(int h)   // float offset of 16B row
{
    return ((h & 3) * 32 + ((h >> 2) ^ (2 * (h & 3)))) * 4;
}

// Forward matvec (smem input): this warp computes rows c0, c0+1 (c0 = 2l + 64wa).
// Weight read is float2 at lane stride 8B -> 256B contiguous = 2 wavefronts.
__device__ __forceinline__ void fwd2(const float* __restrict__ Wt,
                                     const float* __restrict__ biasg,
                                     const float* __restrict__ inq,
                                     ull z[2][4], int c0)
{
    float2 bb = *(const float2*)&biasg[c0];
    z[0][0] = z[0][1] = z[0][2] = z[0][3] = pack2(bb.x, bb.x);
    z[1][0] = z[1][1] = z[1][2] = z[1][3] = pack2(bb.y, bb.y);

#pragma unroll 4
    for (int k = 0; k < HID; ++k) {
        float2 wv = *(const float2*)&Wt[k*PAD + c0];     // contiguous: 2 wf
        const float* rp = inq + physrow(k)*8;
        int b = cswap(k);
        ulonglong2 xa = *(const ulonglong2*)(rp + 4*b);
        ulonglong2 xb = *(const ulonglong2*)(rp + 4*(b^1));
        ull x[4] = {xa.x, xa.y, xb.x, xb.y};
        ull w0 = pack2(wv.x, wv.x), w1 = pack2(wv.y, wv.y);
#pragma unroll
        for (int pp = 0; pp < 4; ++pp) {
            z[0][pp] = ffma2(w0, x[pp], z[0][pp]);
            z[1][pp] = ffma2(w1, x[pp], z[1][pp]);
        }
    }
}

// Input layer (K=12), x pairs by shuffle.
__device__ __forceinline__ void fwd2x(const float* __restrict__ Wt,
                                      const float* __restrict__ biasg,
                                      ull ua, ull ub, ull z[2][4], int c0)
{
    float2 bb = *(const float2*)&biasg[c0];
    z[0][0] = z[0][1] = z[0][2] = z[0][3] = pack2(bb.x, bb.x);
    z[1][0] = z[1][1] = z[1][2] = z[1][3] = pack2(bb.y, bb.y);

#pragma unroll
    for (int k = 0; k < NS; ++k) {
        ull x[4];
#pragma unroll
        for (int pp = 0; pp < 4; ++pp)
            x[pp] = (k < 8) ? shflx(ua, 4*k + pp) : shflx(ub, 4*(k-8) + pp);
        float2 wv = *(const float2*)&Wt[k*PAD + c0];
        ull w0 = pack2(wv.x, wv.x), w1 = pack2(wv.y, wv.y);
#pragma unroll
        for (int pp = 0; pp < 4; ++pp) {
            z[0][pp] = ffma2(w0, x[pp], z[0][pp]);
            z[1][pp] = ffma2(w1, x[pp], z[1][pp]);
        }
    }
}

// Backward vecmat: r[m'][pp] = sum_h g[h][pp] * Wt[(l + 64wa + 32m')][h]
__device__ __forceinline__ void bwd2(const float* __restrict__ Wt,
                                     const float* __restrict__ gin,
                                     ull r[2][4], int l, int wa)
{
    r[0][0]=r[0][1]=r[0][2]=r[0][3]=0ull;
    r[1][0]=r[1][1]=r[1][2]=r[1][3]=0ull;
    int k0 = l + 64*wa;        // m'=0 row; m'=1 row = k0+32

#pragma unroll 2
    for (int c = 0; c < 32; ++c) {          // chunks of 4 h-rows
        int perm = c & 3, b = (c ^ (c >> 2)) & 1;
        ull g[4][4];
#pragma unroll
        for (int sg = 0; sg < 4; ++sg) {
            const float* rp = gin + (4*c + (sg ^ perm))*8;   // = physrow(4c+sg)
            ulonglong2 ga = *(const ulonglong2*)(rp + 4*b);
            ulonglong2 gb = *(const ulonglong2*)(rp + 4*(b^1));
            g[sg][0] = ga.x; g[sg][1] = ga.y; g[sg][2] = gb.x; g[sg][3] = gb.y;
        }
#pragma unroll
        for (int m = 0; m < 2; ++m) {
            float4 w4 = *(const float4*)&Wt[(k0 + 32*m)*PAD + 4*c]; // conflict-free
            float wm[4] = {w4.x, w4.y, w4.z, w4.w};
#pragma unroll
            for (int sg = 0; sg < 4; ++sg) {
                ull w2 = pack2(wm[sg], wm[sg]);
#pragma unroll
                for (int pp = 0; pp < 4; ++pp)
                    r[m][pp] = ffma2(w2, g[sg][pp], r[m][pp]);
            }
        }
    }
}

__global__ __launch_bounds__(THREADS, 1)
void mlp_kernel(const float* __restrict__ state,
                const float* __restrict__ safe_m, const float* __restrict__ safe_l,
                const float* __restrict__ W0, const float* __restrict__ b0,
                const float* __restrict__ W1, const float* __restrict__ b1,
                const float* __restrict__ W2, const float* __restrict__ b2,
                float* __restrict__ out, int nb)
{
    extern __shared__ float s[];
    int tid = threadIdx.x;

    // ---- stage weights into SMEM (transposed, PAD-pitched) ----
    for (int i = tid; i < HID*HID; i += THREADS) {
        int h = i >> 7, k = i & 127;
        s[OW1 + k*PAD + h] = W1[i];
        s[OW2 + k*PAD + h] = W2[i];
    }
    for (int i = tid; i < HID*NS; i += THREADS) {
        int h = i / NS, k = i - h*NS;
        s[OW0 + k*PAD + h] = W0[i];
    }
    if (tid < NS) {
        float m = safe_m[tid], lo = safe_l[tid];
        s[OCEN + tid] = 0.5f * (m + lo);
        s[OINV + tid] = 2.0f / (m - lo);
    }
    __syncthreads();

    int w = tid >> 5, l = tid & 31;
    int pair = w >> 1, wa = w & 1;
    float* BigA = s + OWARP + pair*WSTRIDE;  // [128][8] fp32: V0 -> V1 -> g2 -> g1 -> g0
    float* V1h  = BigA + 1024;               // fp16 rows (later J-partial float area)
    float* VX   = BigA + 1536;               // 16 floats exchange

    int c0 = 2*l + 64*wa;                    // this warp's forward rows (contiguous half)

    int gw = blockIdx.x + GRID * pair;       // one task per warp-pair
    int quads = (nb + NB - 1) / NB;
    if (gw < quads) {
        int base = gw * NB;

        // ---- A: inputs into 2 register pairs per lane (both warps identically) ----
        ull ua, ub;
        {
            int p0 = 2*(l & 3);
            int ka = l >> 2;                  // 0..7
            int kb = 8 + ((l >> 2) & 3);      // 8..11
            int i0 = base + p0, i1 = base + p0 + 1;
            float a0 = (i0 < nb) ? state[i0*NS + ka] : 0.f;
            float a1 = (i1 < nb) ? state[i1*NS + ka] : 0.f;
            float cc0 = (i0 < nb) ? state[i0*NS + kb] : 0.f;
            float cc1 = (i1 < nb) ? state[i1*NS + kb] : 0.f;
            float ca = s[OCEN + ka], ia = s[OINV + ka];
            float cb = s[OCEN + kb], ib = s[OINV + kb];
            ua = pack2((a0 - ca)*ia, (a1 - ca)*ia);
            ub = pack2((cc0 - cb)*ib, (cc1 - cb)*ib);
        }

        ull z[2][4];
        float t[8];

        // ---- B: input layer + tanh -> V0 (BigA rows c0, c0+1) ----
        fwd2x(s + OW0, b0, ua, ub, z, c0);
#pragma unroll
        for (int j = 0; j < 2; ++j) {
#pragma unroll
            for (int pp = 0; pp < 4; ++pp) unpack2(z[j][pp], t[2*pp], t[2*pp+1]);
#pragma unroll
            for (int p = 0; p < 8; ++p) t[p] = ftanh(t[p]);
            store8(BigA, c0 + j, t);
        }
        bar_pair(pair);

        // ---- C: layer 1 + tanh -> V1 (in place) + fp16 copy ----
        fwd2(s + OW1, b1, BigA, z, c0);
        bar_pair(pair);                       // all V0 reads done (both warps)
#pragma unroll
        for (int j = 0; j < 2; ++j) {
#pragma unroll
            for (int pp = 0; pp < 4; ++pp) unpack2(z[j][pp], t[2*pp], t[2*pp+1]);
#pragma unroll
            for (int p = 0; p < 8; ++p) t[p] = ftanh(t[p]);
            store8(BigA, c0 + j, t);
            __half2 h0 = __floats2half2_rn(t[0], t[1]);
            __half2 h1 = __floats2half2_rn(t[2], t[3]);
            __half2 h2 = __floats2half2_rn(t[4], t[5]);
            __half2 h3 = __floats2half2_rn(t[6], t[7]);
            uint4 u;
            u.x = *(unsigned*)&h0; u.y = *(unsigned*)&h1;
            u.z = *(unsigned*)&h2; u.w = *(unsigned*)&h3;
            *(uint4*)&V1h[off16f(c0 + j)] = u;
        }
        bar_pair(pair);

        // ---- D: layer 2 + tanh; vout = R3.V2 ; g2 -> BigA ----
        fwd2(s + OW2, b2, BigA, z, c0);
        bar_pair(pair);                       // all V1 reads done
        {
            ull vo[4] = {0ull, 0ull, 0ull, 0ull};
            float2 r2 = *(const float2*)&g_R3[c0];
            float rj[2] = {r2.x, r2.y};
#pragma unroll
            for (int j = 0; j < 2; ++j) {
                ull rj2 = pack2(rj[j], rj[j]);
#pragma unroll
                for (int pp = 0; pp < 4; ++pp) unpack2(z[j][pp], t[2*pp], t[2*pp+1]);
#pragma unroll
                for (int p = 0; p < 8; ++p) t[p] = ftanh(t[p]);
#pragma unroll
                for (int pp = 0; pp < 4; ++pp)
                    vo[pp] = ffma2(rj2, pack2(t[2*pp], t[2*pp+1]), vo[pp]);
                float gq[8];
#pragma unroll
                for (int p = 0; p < 8; ++p) gq[p] = rj[j] * (1.f - t[p]*t[p]);
                store8(BigA, c0 + j, gq);
            }
            float vout[8];
#pragma unroll
            for (int pp = 0; pp < 4; ++pp) unpack2(vo[pp], vout[2*pp], vout[2*pp+1]);
#pragma unroll
            for (int p = 0; p < 8; ++p) {
                float v = vout[p];
#pragma unroll
                for (int off = 16; off > 0; off >>= 1)
                    v += __shfl_xor_sync(0xffffffffu, v, off);
                vout[p] = v;
            }
            if (wa == 1 && l < 8) VX[l] = vout[l];
            bar_pair(pair);                   // g2 + VX visible
            if (wa == 0 && l < 8 && base + l < nb)
                out[(base + l)*13] = vout[l] + VX[l] + g_c3;
        }

        ull r[2][4];

        // ---- E: r = g2.W2 ; s1 from fp16; g1 -> BigA ----
        bwd2(s + OW2, BigA, r, l, wa);
        bar_pair(pair);                       // all g2 reads done
#pragma unroll
        for (int m = 0; m < 2; ++m) {
            int h = l + 64*wa + 32*m;
            uint4 u = *(const uint4*)&V1h[off16f(h)];
            float2 f0 = __half22float2(*(__half2*)&u.x);
            float2 f1 = __half22float2(*(__half2*)&u.y);
            float2 f2 = __half22float2(*(__half2*)&u.z);
            float2 f3 = __half22float2(*(__half2*)&u.w);
            float vp[8] = {f0.x, f0.y, f1.x, f1.y, f2.x, f2.y, f3.x, f3.y};
            float gq[8];
#pragma unroll
            for (int pp = 0; pp < 4; ++pp) {
                float r0, r1; unpack2(r[m][pp], r0, r1);
                gq[2*pp]   = r0 * (1.f - vp[2*pp]*vp[2*pp]);
                gq[2*pp+1] = r1 * (1.f - vp[2*pp+1]*vp[2*pp+1]);
            }
            store8(BigA, h, gq);
        }
        bar_pair(pair);

        // ---- F: r = g1.W1 ; s0 recompute (shfl x) ; g0 -> BigA ----
        bwd2(s + OW1, BigA, r, l, wa);
        bar_pair(pair);                       // all g1 reads done
        {
            ull z0[2][4];
#pragma unroll
            for (int m = 0; m < 2; ++m) {
                float bm = b0[l + 64*wa + 32*m];
                ull b2v = pack2(bm, bm);
#pragma unroll
                for (int pp = 0; pp < 4; ++pp) z0[m][pp] = b2v;
            }
#pragma unroll
            for (int k = 0; k < NS; ++k) {
                ull x[4];
#pragma unroll
                for (int pp = 0; pp < 4; ++pp)
                    x[pp] = (k < 8) ? shflx(ua, 4*k + pp) : shflx(ub, 4*(k-8) + pp);
#pragma unroll
                for (int m = 0; m < 2; ++m) {
                    float wv = s[OW0 + k*PAD + l + 64*wa + 32*m];
                    ull w2 = pack2(wv, wv);
#pragma unroll
                    for (int pp = 0; pp < 4; ++pp)
                        z0[m][pp] = ffma2(w2, x[pp], z0[m][pp]);
                }
            }
#pragma unroll
            for (int m = 0; m < 2; ++m) {
                int h = l + 64*wa + 32*m;
                float gq[8];
#pragma unroll
                for (int pp = 0; pp < 4; ++pp) {
                    float a, b; unpack2(z0[m][pp], a, b);
                    a = ftanh(a); b = ftanh(b);
                    float r0, r1; unpack2(r[m][pp], r0, r1);
                    gq[2*pp]   = r0 * (1.f - a*a);
                    gq[2*pp+1] = r1 * (1.f - b*b);
                }
                store8(BigA, h, gq);
            }
        }
        bar_pair(pair);

        // ---- final: J[k][p] = (sum_h g0[h][p] * W0t[k][h]) * inv[k] ----
        {
            int p  = l & 7;
            int k0 = l >> 3;                 // k = k0 + 4c, c in 0..2
            int psel = p >> 2, pw = p & 3;
            float acc[3] = {0.f, 0.f, 0.f};
            int ibeg = 16*wa;
#pragma unroll 2
            for (int ii = 0; ii < 16; ++ii) {   // h = 4i..4i+3, this warp's 64-row half
                int i = ibeg + ii;
                float4 w0 = *(const float4*)&s[OW0 + (k0    )*PAD + 4*i];
                float4 w1 = *(const float4*)&s[OW0 + (k0 + 4)*PAD + 4*i];
                float4 w2 = *(const float4*)&s[OW0 + (k0 + 8)*PAD + 4*i];
                float gv[4];
#pragma unroll
                for (int d = 0; d < 4; ++d) {
                    int h = 4*i + d;
                    gv[d] = BigA[physrow(h)*8 + 4*(psel ^ cswap(h)) + pw];
                }
                acc[0] = fmaf(w0.x, gv[0], acc[0]); acc[0] = fmaf(w0.y, gv[1], acc[0]);
                acc[0] = fmaf(w0.z, gv[2], acc[0]); acc[0] = fmaf(w0.w, gv[3], acc[0]);
                acc[1] = fmaf(w1.x, gv[0], acc[1]); acc[1] = fmaf(w1.y, gv[1], acc[1]);
                acc[1] = fmaf(w1.z, gv[2], acc[1]); acc[1] = fmaf(w1.w, gv[3], acc[1]);
                acc[2] = fmaf(w2.x, gv[0], acc[2]); acc[2] = fmaf(w2.y, gv[1], acc[2]);
                acc[2] = fmaf(w2.z, gv[2], acc[2]); acc[2] = fmaf(w2.w, gv[3], acc[2]);
            }
            float* Jp = V1h;                  // reuse fp16 area as float scratch
            if (wa == 1) {
#pragma unroll
                for (int c = 0; c < 3; ++c) Jp[l*3 + c] = acc[c];
            }
            bar_pair(pair);
            if (wa == 0 && base + p < nb) {
#pragma unroll
                for (int c = 0; c < 3; ++c) {
                    int k = k0 + 4*c;
                    out[(base + p)*13 + 1 + k] = (acc[c] + Jp[l*3 + c]) * s[OINV + k];
                }
            }
        }
    }
}

extern "C" void kernel_launch(void* const* d_in, const int* in_sizes, int n_in,
                              void* d_out, int out_size)
{
    const float* state  = (const float*)d_in[0];
    const float* safe_m = (const float*)d_in[1];
    const float* safe_l = (const float*)d_in[2];
    const float* W0     = (const float*)d_in[3];
    const float* b0     = (const float*)d_in[4];
    const float* W1     = (const float*)d_in[5];
    const float* b1     = (const float*)d_in[6];
    const float* W2     = (const float*)d_in[7];
    const float* b2     = (const float*)d_in[8];
    const float* W3     = (const float*)d_in[9];
    const float* b3     = (const float*)d_in[10];
    const float* Wout   = (const float*)d_in[11];
    const float* bout   = (const float*)d_in[12];
    float* out = (float*)d_out;

    int nb = in_sizes[0] / NS;

    cudaFuncSetAttribute(mlp_kernel, cudaFuncAttributeMaxDynamicSharedMemorySize,
                         SMEM_FLOATS * (int)sizeof(float));

    init_kernel<<<1, HID>>>(W3, b3, Wout, bout);
    mlp_kernel<<<GRID, THREADS, SMEM_FLOATS * sizeof(float)>>>(
        state, safe_m, safe_l, W0, b0, W1, b1, W2, b2, out, nb);
}